// round 1
// baseline (speedup 1.0000x reference)
#include <cuda_runtime.h>

#define HW    256
#define BATCH 8
#define CH    64
#define HWHW  (HW * HW)   // 65536

// Scratch for channel-wise L1 norms: [B, H, W] each, 2 MB apiece.
__device__ float g_n1[BATCH * HWHW];
__device__ float g_n2[BATCH * HWHW];

// ---------------------------------------------------------------------------
// K1: n1[b,p] = sum_c |x1[b,c,p]|, n2 likewise. float4 vectorized,
// each thread owns 4 consecutive pixels, loops 64 channels.
// ---------------------------------------------------------------------------
__global__ void __launch_bounds__(256) k_norm(const float* __restrict__ x1,
                                              const float* __restrict__ x2) {
    int g  = blockIdx.x * blockDim.x + threadIdx.x;   // one thread per 4 pixels
    int b  = g >> 14;                                 // 16384 threads per batch
    int p4 = (g & 16383) << 2;

    const float4* p1 = reinterpret_cast<const float4*>(x1 + (size_t)b * CH * HWHW + p4);
    const float4* p2 = reinterpret_cast<const float4*>(x2 + (size_t)b * CH * HWHW + p4);

    float4 s1 = make_float4(0.f, 0.f, 0.f, 0.f);
    float4 s2 = make_float4(0.f, 0.f, 0.f, 0.f);

#pragma unroll 8
    for (int c = 0; c < CH; c++) {
        float4 a = p1[c * (HWHW / 4)];
        float4 v = p2[c * (HWHW / 4)];
        s1.x += fabsf(a.x); s1.y += fabsf(a.y); s1.z += fabsf(a.z); s1.w += fabsf(a.w);
        s2.x += fabsf(v.x); s2.y += fabsf(v.y); s2.z += fabsf(v.z); s2.w += fabsf(v.w);
    }

    reinterpret_cast<float4*>(g_n1 + b * HWHW + p4)[0] = s1;
    reinterpret_cast<float4*>(g_n2 + b * HWHW + p4)[0] = s2;
}

// ---------------------------------------------------------------------------
// K2: per-pixel 3x3 conv on n1/n2 (zero pad) + bias -> c1, c2;
// f1 = c1/(c1+c2), f2 = c2/(c1+c2); out = x1*f1 + x2*f2 over all channels.
// Block = one batch x 4-row stripe (4x256 = 1024 pixels, 256 threads,
// 4 pixels/thread). f1/f2 live in registers: phase-1 and phase-2 pixel
// ownership are identical (thread t owns pixels t*4..t*4+3 of the stripe).
// ---------------------------------------------------------------------------
#define TR 4  // rows per block

__global__ void __launch_bounds__(256) k_conv_combine(const float* __restrict__ x1,
                                                      const float* __restrict__ x2,
                                                      const float* __restrict__ w,
                                                      const float* __restrict__ bias,
                                                      float* __restrict__ out) {
    int bid = blockIdx.x;
    int b   = bid >> 6;            // 64 row-tiles per batch (256 / TR)
    int r0  = (bid & 63) * TR;
    int tid = threadIdx.x;

    float wv[9];
#pragma unroll
    for (int i = 0; i < 9; i++) wv[i] = w[i];
    float bv = bias[0];

    const float* __restrict__ n1 = g_n1 + b * HWHW;
    const float* __restrict__ n2 = g_n2 + b * HWHW;

    // Phase 1: blend factors for this thread's 4 pixels (registers only).
    float f1r[4], f2r[4];
#pragma unroll
    for (int k = 0; k < 4; k++) {
        int idx = tid * 4 + k;           // 0..1023 within stripe
        int r   = r0 + (idx >> 8);       // global row
        int cc  = idx & 255;             // global col
        float c1 = bv, c2 = bv;
#pragma unroll
        for (int di = 0; di < 3; di++) {
            int rr = r + di - 1;
            if (rr < 0 || rr >= HW) continue;
#pragma unroll
            for (int dj = 0; dj < 3; dj++) {
                int cj = cc + dj - 1;
                if (cj < 0 || cj >= HW) continue;
                float ww = wv[di * 3 + dj];
                c1 += ww * n1[rr * HW + cj];
                c2 += ww * n2[rr * HW + cj];
            }
        }
        float rd = 1.0f / (c1 + c2);
        f1r[k] = c1 * rd;
        f2r[k] = c2 * rd;
    }

    // Phase 2: stream all 64 channels through the stripe.
    size_t base = (size_t)b * CH * HWHW + (size_t)r0 * HW;
    const float4* p1 = reinterpret_cast<const float4*>(x1 + base);
    const float4* p2 = reinterpret_cast<const float4*>(x2 + base);
    float4*       po = reinterpret_cast<float4*>(out + base);

#pragma unroll 4
    for (int c = 0; c < CH; c++) {
        float4 a = p1[c * (HWHW / 4) + tid];
        float4 v = p2[c * (HWHW / 4) + tid];
        float4 o;
        o.x = a.x * f1r[0] + v.x * f2r[0];
        o.y = a.y * f1r[1] + v.y * f2r[1];
        o.z = a.z * f1r[2] + v.z * f2r[2];
        o.w = a.w * f1r[3] + v.w * f2r[3];
        po[c * (HWHW / 4) + tid] = o;
    }
}

extern "C" void kernel_launch(void* const* d_in, const int* in_sizes, int n_in,
                              void* d_out, int out_size) {
    const float* x1   = (const float*)d_in[0];
    const float* x2   = (const float*)d_in[1];
    const float* w    = (const float*)d_in[2];
    const float* bias = (const float*)d_in[3];
    float*       out  = (float*)d_out;

    // K1: 8 batches * 65536 pixels / 4 per thread / 256 threads = 512 blocks
    k_norm<<<512, 256>>>(x1, x2);
    // K2: 8 batches * 64 row-tiles = 512 blocks
    k_conv_combine<<<512, 256>>>(x1, x2, w, bias, out);
}

// round 2
// speedup vs baseline: 1.0060x; 1.0060x over previous
#include <cuda_runtime.h>

#define HW     256
#define NB     8
#define CH     64
#define HWHW   65536
#define NUNITS (NB * HW)     // 2048 row-units (b*256 + row)
#define GRID   296           // persistent blocks, all resident (2/SM)
#define THREADS 512

// Norm rows: g_n[(b*256+row)*256 + col], 2 MB each. Flags: one per row-unit.
__device__ float g_n1[NUNITS * HW];
__device__ float g_n2[NUNITS * HW];
__device__ int   g_flag[NUNITS];

__global__ void k_reset() {
    g_flag[blockIdx.x * blockDim.x + threadIdx.x] = 0;
}

__global__ void __launch_bounds__(THREADS, 2)
k_fused(const float* __restrict__ x1, const float* __restrict__ x2,
        const float* __restrict__ w,  const float* __restrict__ bias,
        float* __restrict__ out) {
    __shared__ float4 f1s[64], f2s[64];
    const int tid = threadIdx.x;
    const int bid = blockIdx.x;

    float wv[9];
#pragma unroll
    for (int i = 0; i < 9; i++) wv[i] = w[i];
    const float bv = bias[0];

    const int iters = (NUNITS + GRID - 1) / GRID;   // 7

    for (int it = 0; it <= iters; ++it) {
        // ---------------- produce: norm row for unit up ----------------
        const int up = bid + it * GRID;
        const bool do_prod = (it < iters) && (up < NUNITS);
        if (do_prod) {
            const int b = up >> 8, row = up & 255;
            const int p = tid & 255;
            const float* src = (tid < 256) ? x1 : x2;
            float*       dst = (tid < 256) ? g_n1 : g_n2;
            const size_t base = (size_t)b * CH * HWHW + (size_t)row * HW + p;
            float s = 0.f;
#pragma unroll 16
            for (int c = 0; c < CH; ++c)
                s += fabsf(__ldg(src + base + (size_t)c * HWHW));
            dst[up * HW + p] = s;
            __threadfence();            // publish norm stores (per thread)
        }
        __syncthreads();
        if (do_prod && tid == 0)
            atomicExch(&g_flag[up], 1); // release flag after all stores fenced

        // ---------------- consume: conv + blend for unit uc ----------------
        if (it >= 1) {
            const int uc = bid + (it - 1) * GRID;
            if (uc < NUNITS) {
                const int b = uc >> 8, row = uc & 255;
                if (tid == 0) {
                    if (row > 0)   while (*(volatile int*)&g_flag[uc - 1] == 0) {}
                    if (row < 255) while (*(volatile int*)&g_flag[uc + 1] == 0) {}
                    __threadfence();    // acquire
                }
                __syncthreads();

                // blend factors for 256 pixels: threads 0..63, 4 px each
                if (tid < 64) {
                    float4 F1, F2;
                    float* pf1 = (float*)&F1;
                    float* pf2 = (float*)&F2;
#pragma unroll
                    for (int k = 0; k < 4; ++k) {
                        const int col = tid * 4 + k;
                        float c1 = bv, c2 = bv;
#pragma unroll
                        for (int di = 0; di < 3; ++di) {
                            const int rr = row + di - 1;
                            if (rr < 0 || rr >= HW) continue;
                            const float* n1r = g_n1 + (size_t)(b * HW + rr) * HW;
                            const float* n2r = g_n2 + (size_t)(b * HW + rr) * HW;
#pragma unroll
                            for (int dj = 0; dj < 3; ++dj) {
                                const int cc = col + dj - 1;
                                if (cc < 0 || cc >= HW) continue;
                                const float ww = wv[di * 3 + dj];
                                c1 += ww * n1r[cc];
                                c2 += ww * n2r[cc];
                            }
                        }
                        const float rd = 1.0f / (c1 + c2);
                        pf1[k] = c1 * rd;
                        pf2[k] = c2 * rd;
                    }
                    f1s[tid] = F1;
                    f2s[tid] = F2;
                }
                __syncthreads();

                // stream 64 channels of this row: thread = (f4-group g, channel-octet cs)
                const int g  = tid & 63;
                const int cs = tid >> 6;
                const float4 F1 = f1s[g];
                const float4 F2 = f2s[g];
                const size_t fbase = ((size_t)b * CH + cs * 8) * (HWHW / 4)
                                   + (size_t)row * (HW / 4) + g;
                const float4* p1 = (const float4*)x1 + fbase;
                const float4* p2 = (const float4*)x2 + fbase;
                float4*       po = (float4*)out + fbase;
#pragma unroll
                for (int c = 0; c < 8; ++c) {
                    const float4 a = __ldcs(p1 + (size_t)c * (HWHW / 4));
                    const float4 v = __ldcs(p2 + (size_t)c * (HWHW / 4));
                    float4 o;
                    o.x = a.x * F1.x + v.x * F2.x;
                    o.y = a.y * F1.y + v.y * F2.y;
                    o.z = a.z * F1.z + v.z * F2.z;
                    o.w = a.w * F1.w + v.w * F2.w;
                    __stcs(po + (size_t)c * (HWHW / 4), o);
                }
            }
        }
    }
}

extern "C" void kernel_launch(void* const* d_in, const int* in_sizes, int n_in,
                              void* d_out, int out_size) {
    const float* x1   = (const float*)d_in[0];
    const float* x2   = (const float*)d_in[1];
    const float* w    = (const float*)d_in[2];
    const float* bias = (const float*)d_in[3];
    float*       out  = (float*)d_out;

    k_reset<<<NUNITS / 256, 256>>>();
    k_fused<<<GRID, THREADS>>>(x1, x2, w, bias, out);
}

// round 3
// speedup vs baseline: 1.1000x; 1.0935x over previous
#include <cuda_runtime.h>

#define HW      256
#define NB      8
#define CH      64
#define HWHW    65536
#define NUNITS  (NB * HW)     // 2048 row-units (b*256 + row)
#define GRID    296           // persistent blocks, all resident (2/SM)
#define THREADS 512

// Norm rows: g_n[(b*256+row)*256 + col], 2 MB each. Flags: one per row-unit.
__device__ float g_n1[NUNITS * HW];
__device__ float g_n2[NUNITS * HW];
__device__ int   g_flag[NUNITS];

__global__ void k_reset() {
    g_flag[blockIdx.x * blockDim.x + threadIdx.x] = 0;
}

__global__ void __launch_bounds__(THREADS, 2)
k_fused(const float* __restrict__ x1, const float* __restrict__ x2,
        const float* __restrict__ w,  const float* __restrict__ bias,
        float* __restrict__ out) {
    const int tid = threadIdx.x;
    const int bid = blockIdx.x;

    float wv[9];
#pragma unroll
    for (int i = 0; i < 9; i++) wv[i] = w[i];
    const float bv = bias[0];

    const int iters = (NUNITS + GRID - 1) / GRID;   // 7

    for (int it = 0; it <= iters; ++it) {
        if (tid < 256) {
            // ============ PRODUCER warps: norm row for unit up ============
            const int up = bid + it * GRID;
            if (it < iters && up < NUNITS) {
                const int b = up >> 8, row = up & 255;
                const size_t base = (size_t)b * CH * HWHW + (size_t)row * HW + tid;
                const float* s1p = x1 + base;
                const float* s2p = x2 + base;
                float s1 = 0.f, s2 = 0.f;
#pragma unroll 16
                for (int c = 0; c < CH; ++c) {
                    s1 += fabsf(__ldg(s1p + (size_t)c * HWHW));
                    s2 += fabsf(__ldg(s2p + (size_t)c * HWHW));
                }
                g_n1[up * HW + tid] = s1;
                g_n2[up * HW + tid] = s2;
                __threadfence();                        // publish this thread's stores
                asm volatile("bar.sync 1, 256;" ::: "memory");  // producer-only barrier
                if (tid == 0)
                    atomicExch(&g_flag[up], 1);         // release
            }
        } else if (it >= 1) {
            // ============ CONSUMER warps: conv + blend for unit uc ============
            const int uc = bid + (it - 1) * GRID;
            if (uc < NUNITS) {
                const int b = uc >> 8, row = uc & 255;
                const int t = tid - 256;
                const int g  = t & 63;     // float4 group (pixels 4g..4g+3)
                const int cs = t >> 6;     // channel slice 0..3 (16 ch each)

                // wait for neighbor norm rows (own row produced by this block
                // last iteration — visible via the iteration __syncthreads)
                if (row > 0)   while (*(volatile int*)&g_flag[uc - 1] == 0) {}
                if (row < 255) while (*(volatile int*)&g_flag[uc + 1] == 0) {}
                __threadfence();           // acquire

                // blend factors for this thread's 4 pixels (redundant per cs,
                // all loads L1/L2 hits on 3KB rows)
                float4 F1, F2;
                float* pf1 = (float*)&F1;
                float* pf2 = (float*)&F2;
#pragma unroll
                for (int k = 0; k < 4; ++k) {
                    const int col = g * 4 + k;
                    float c1 = bv, c2 = bv;
#pragma unroll
                    for (int di = 0; di < 3; ++di) {
                        const int rr = row + di - 1;
                        if (rr < 0 || rr >= HW) continue;
                        const float* n1r = g_n1 + (size_t)(b * HW + rr) * HW;
                        const float* n2r = g_n2 + (size_t)(b * HW + rr) * HW;
#pragma unroll
                        for (int dj = 0; dj < 3; ++dj) {
                            const int cc = col + dj - 1;
                            if (cc < 0 || cc >= HW) continue;
                            const float ww = wv[di * 3 + dj];
                            c1 += ww * n1r[cc];
                            c2 += ww * n2r[cc];
                        }
                    }
                    const float rd = 1.0f / (c1 + c2);
                    pf1[k] = c1 * rd;
                    pf2[k] = c2 * rd;
                }

                // stream 16 channels of this row (L2-hit reads, streaming writes)
                const size_t fbase = ((size_t)b * CH + cs * 16) * (HWHW / 4)
                                   + (size_t)row * (HW / 4) + g;
                const float4* p1 = (const float4*)x1 + fbase;
                const float4* p2 = (const float4*)x2 + fbase;
                float4*       po = (float4*)out + fbase;
#pragma unroll 8
                for (int c = 0; c < 16; ++c) {
                    const float4 a = __ldcs(p1 + (size_t)c * (HWHW / 4));
                    const float4 v = __ldcs(p2 + (size_t)c * (HWHW / 4));
                    float4 o;
                    o.x = a.x * F1.x + v.x * F2.x;
                    o.y = a.y * F1.y + v.y * F2.y;
                    o.z = a.z * F1.z + v.z * F2.z;
                    o.w = a.w * F1.w + v.w * F2.w;
                    __stcs(po + (size_t)c * (HWHW / 4), o);
                }
            }
        }
        __syncthreads();   // iteration boundary: it-produce visible to it+1-consume
    }
}

extern "C" void kernel_launch(void* const* d_in, const int* in_sizes, int n_in,
                              void* d_out, int out_size) {
    const float* x1   = (const float*)d_in[0];
    const float* x2   = (const float*)d_in[1];
    const float* w    = (const float*)d_in[2];
    const float* bias = (const float*)d_in[3];
    float*       out  = (float*)d_out;

    k_reset<<<NUNITS / 256, 256>>>();
    k_fused<<<GRID, THREADS>>>(x1, x2, w, bias, out);
}